// round 1
// baseline (speedup 1.0000x reference)
#include <cuda_runtime.h>
#include <math.h>

#define BB 4
#define SS 2048
#define EE 512
#define HH 8
#define HD 64
#define SCALE 0.04419417382415922f  /* 512^-0.5 (reference scales by E, not HD) */

// Scratch (static device arrays — allocation rules forbid cudaMalloc)
__device__ float g_q[BB * HH * SS * HD];
__device__ float g_k[BB * HH * SS * HD];
__device__ float g_v[BB * HH * SS * HD];

// ---------------------------------------------------------------------------
// Kernel 1: fused QKV projection.
// C[m][n] = sum_e x[m][e] * W[n][e], written as [b][h][s][d] scratch layout.
// 64x64 tile, BK=32, 256 threads, 4x4 microtile.
// ---------------------------------------------------------------------------
__global__ void __launch_bounds__(256) qkv_kernel(
    const float* __restrict__ x,
    const float* __restrict__ Wq,
    const float* __restrict__ Wk,
    const float* __restrict__ Wv)
{
    const float* W = blockIdx.z == 0 ? Wq : (blockIdx.z == 1 ? Wk : Wv);
    float* out = blockIdx.z == 0 ? g_q : (blockIdx.z == 1 ? g_k : g_v);
    const int m0 = blockIdx.y * 64;
    const int n0 = blockIdx.x * 64;

    __shared__ float As[32][65];  // [k][i]
    __shared__ float Bs[32][65];  // [k][j]

    const int tid = threadIdx.x;
    const int ty = tid >> 4, tx = tid & 15;

    float acc[4][4] = {};

    for (int k0 = 0; k0 < EE; k0 += 32) {
        #pragma unroll
        for (int t = tid; t < 2048; t += 256) {
            int i = t >> 5, k = t & 31;
            As[k][i] = x[(size_t)(m0 + i) * EE + k0 + k];
            Bs[k][i] = W[(size_t)(n0 + i) * EE + k0 + k];
        }
        __syncthreads();
        #pragma unroll 8
        for (int k = 0; k < 32; k++) {
            float a[4], b[4];
            #pragma unroll
            for (int u = 0; u < 4; u++) { a[u] = As[k][ty * 4 + u]; b[u] = Bs[k][tx * 4 + u]; }
            #pragma unroll
            for (int u = 0; u < 4; u++)
                #pragma unroll
                for (int v = 0; v < 4; v++)
                    acc[u][v] += a[u] * b[v];
        }
        __syncthreads();
    }

    #pragma unroll
    for (int u = 0; u < 4; u++) {
        int m = m0 + ty * 4 + u;
        int b_ = m / SS, s_ = m % SS;
        #pragma unroll
        for (int v = 0; v < 4; v++) {
            int n = n0 + tx * 4 + v;
            int h = n / HD, d = n & (HD - 1);
            out[(((size_t)b_ * HH + h) * SS + s_) * HD + d] = acc[u][v];
        }
    }
}

// ---------------------------------------------------------------------------
// Kernel 2: flash attention with relative position (skew) term.
//
// Srel[i,j] = q_i  . Er[S-1-(i-j)]   if j <= i
//           = 0                      if j == i+1
//           = q_{i+1} . Er[j-i-2]    if j >= i+2
//
// Per (qtile i0, ktile j0), both cases index a 127-wide sliding Er window with
// the SAME local index 63 + (j'-i'):
//   W1[t] = Er[(S-1-i0+j0-63) + t],  W2[t] = Er[(j0-i0-65) + t]
// ---------------------------------------------------------------------------
#define QS_P 69
#define KS_P 67
#define VS_P 65
#define PT_P 65
#define W_P 133
#define SMEM_FLOATS 34048  /* 4416+4288+4160+4160+8512+8512 */
#define SMEM_BYTES (SMEM_FLOATS * 4)

template <bool D1, bool D2>
__device__ __forceinline__ void score_tile(
    const float* __restrict__ Qs, const float* __restrict__ Ks,
    const float* __restrict__ W1, const float* __restrict__ W2,
    int ty4, int tx4, int toff,
    float (&s_acc)[4][4], float (&r1)[4][4], float (&r2)[4][4])
{
    #pragma unroll 2
    for (int d = 0; d < 64; d++) {
        float qv[5], kv[4], w1v[7], w2v[7];
        #pragma unroll
        for (int u = 0; u < 4; u++) qv[u] = Qs[d * QS_P + ty4 + u];
        if (D2) qv[4] = Qs[d * QS_P + ty4 + 4];
        #pragma unroll
        for (int u = 0; u < 4; u++) kv[u] = Ks[d * KS_P + tx4 + u];
        if (D1) {
            #pragma unroll
            for (int u = 0; u < 7; u++) w1v[u] = W1[d * W_P + toff - 3 + u];
        }
        if (D2) {
            #pragma unroll
            for (int u = 0; u < 7; u++) w2v[u] = W2[d * W_P + toff - 3 + u];
        }
        #pragma unroll
        for (int a = 0; a < 4; a++)
            #pragma unroll
            for (int v = 0; v < 4; v++) {
                s_acc[a][v] += qv[a] * kv[v];
                if (D1) r1[a][v] += qv[a] * w1v[3 + v - a];
                if (D2) r2[a][v] += qv[a + 1] * w2v[3 + v - a];
            }
    }
}

__global__ void __launch_bounds__(256, 1) attn_kernel(
    const float* __restrict__ Er, float* __restrict__ out)
{
    extern __shared__ float sm[];
    float* Qs = sm;             // [64][QS_P] : [d][r], r in 0..64 (row 64 = q_{i0+64})
    float* Ks = sm + 4416;      // [64][KS_P] : [d][j]
    float* Vs = sm + 8704;      // [64][VS_P] : [j][d]
    float* Pt = sm + 12864;     // [64][PT_P] : [j][i]
    float* W1 = sm + 17024;     // [64][W_P]  : [d][t]
    float* W2 = sm + 25536;     // [64][W_P]

    const int tid = threadIdx.x;
    const int ty = tid >> 4, tx = tid & 15;
    const int ty4 = ty * 4, tx4 = tx * 4;
    const int bh = blockIdx.y;
    const int i0 = blockIdx.x * 64;

    const float* qb = g_q + ((size_t)bh * SS + i0) * HD;
    const float* kb0 = g_k + (size_t)bh * SS * HD;
    const float* vb0 = g_v + (size_t)bh * SS * HD;

    // Load Q tile (65 rows: extra row for the i+1 case; zero past S)
    for (int t = tid; t < 65 * 64; t += 256) {
        int r = t >> 6, d = t & 63;
        float v = (i0 + r < SS) ? qb[(size_t)r * HD + d] : 0.0f;
        Qs[d * QS_P + r] = v;
    }

    float m_old[4], l_sum[4], acc_o[4][4];
    #pragma unroll
    for (int a = 0; a < 4; a++) {
        m_old[a] = -1e30f;
        l_sum[a] = 0.0f;
        #pragma unroll
        for (int v = 0; v < 4; v++) acc_o[a][v] = 0.0f;
    }

    const int toff = 63 + tx4 - ty4;

    for (int j0 = 0; j0 < SS; j0 += 64) {
        __syncthreads();  // previous AV done before overwriting K/V/W/Pt

        // case1 possible iff exists j<=i in tile; case2 iff exists j>=i+2
        const bool need1 = (i0 + 63 >= j0);
        const bool need2 = (j0 + 63 >= i0 + 2);

        for (int t = tid; t < 4096; t += 256) {
            int j = t >> 6, d = t & 63;
            Ks[d * KS_P + j] = kb0[(size_t)(j0 + j) * HD + d];
            Vs[j * VS_P + d] = vb0[(size_t)(j0 + j) * HD + d];
        }
        const int eb1 = (SS - 1 - i0 + j0) - 63;
        const int eb2 = (j0 - i0 - 2) - 63;
        if (need1) {
            for (int t = tid; t < 8192; t += 256) {
                int tt = t >> 6, d = t & 63;
                int e1 = eb1 + tt;
                W1[d * W_P + tt] = (e1 >= 0 && e1 < SS) ? Er[(size_t)e1 * HD + d] : 0.0f;
            }
        }
        if (need2) {
            for (int t = tid; t < 8192; t += 256) {
                int tt = t >> 6, d = t & 63;
                int e2 = eb2 + tt;
                W2[d * W_P + tt] = (e2 >= 0 && e2 < SS) ? Er[(size_t)e2 * HD + d] : 0.0f;
            }
        }
        __syncthreads();

        float s_acc[4][4] = {}, r1[4][4] = {}, r2[4][4] = {};
        if (need1 && need2)
            score_tile<true, true>(Qs, Ks, W1, W2, ty4, tx4, toff, s_acc, r1, r2);
        else if (need1)
            score_tile<true, false>(Qs, Ks, W1, W2, ty4, tx4, toff, s_acc, r1, r2);
        else
            score_tile<false, true>(Qs, Ks, W1, W2, ty4, tx4, toff, s_acc, r1, r2);

        // combine + scale (predicated select, so stale/skipped r1/r2 is safe)
        #pragma unroll
        for (int a = 0; a < 4; a++) {
            int i = i0 + ty4 + a;
            #pragma unroll
            for (int v = 0; v < 4; v++) {
                int j = j0 + tx4 + v;
                float srel = (j <= i) ? r1[a][v] : ((j >= i + 2) ? r2[a][v] : 0.0f);
                s_acc[a][v] = (s_acc[a][v] + srel) * SCALE;
            }
        }

        // online softmax: rows span the 16-lane half-warp (lanes share ty)
        #pragma unroll
        for (int a = 0; a < 4; a++) {
            float mx = fmaxf(fmaxf(s_acc[a][0], s_acc[a][1]),
                             fmaxf(s_acc[a][2], s_acc[a][3]));
            #pragma unroll
            for (int off = 8; off > 0; off >>= 1)
                mx = fmaxf(mx, __shfl_xor_sync(0xffffffffu, mx, off));
            float m_new = fmaxf(m_old[a], mx);
            float corr = __expf(m_old[a] - m_new);
            float rs = 0.0f;
            #pragma unroll
            for (int v = 0; v < 4; v++) {
                float p = __expf(s_acc[a][v] - m_new);
                s_acc[a][v] = p;
                rs += p;
            }
            #pragma unroll
            for (int off = 8; off > 0; off >>= 1)
                rs += __shfl_xor_sync(0xffffffffu, rs, off);
            l_sum[a] = l_sum[a] * corr + rs;
            m_old[a] = m_new;
            #pragma unroll
            for (int v = 0; v < 4; v++) acc_o[a][v] *= corr;
        }

        // stage P transposed for the AV GEMM
        #pragma unroll
        for (int a = 0; a < 4; a++)
            #pragma unroll
            for (int v = 0; v < 4; v++)
                Pt[(tx4 + v) * PT_P + ty4 + a] = s_acc[a][v];
        __syncthreads();

        // O += P @ V
        #pragma unroll 4
        for (int jj = 0; jj < 64; jj++) {
            float pv[4], vv[4];
            #pragma unroll
            for (int u = 0; u < 4; u++) {
                pv[u] = Pt[jj * PT_P + ty4 + u];
                vv[u] = Vs[jj * VS_P + tx4 + u];
            }
            #pragma unroll
            for (int a = 0; a < 4; a++)
                #pragma unroll
                for (int v = 0; v < 4; v++)
                    acc_o[a][v] += pv[a] * vv[v];
        }
    }

    // normalize + merge heads: out[b][s][h*HD+d]
    const int b_ = bh / HH, h = bh % HH;
    #pragma unroll
    for (int a = 0; a < 4; a++) {
        int i = i0 + ty4 + a;
        float inv = 1.0f / l_sum[a];
        #pragma unroll
        for (int v = 0; v < 4; v++)
            out[((size_t)b_ * SS + i) * EE + h * HD + tx4 + v] = acc_o[a][v] * inv;
    }
}

// ---------------------------------------------------------------------------
// Kernel 3: in-place LayerNorm over E=512 per (b,s) row.
// ---------------------------------------------------------------------------
__global__ void __launch_bounds__(256) ln_kernel(
    float* __restrict__ out,
    const float* __restrict__ gamma,
    const float* __restrict__ beta)
{
    __shared__ float red[16];
    const int row = blockIdx.x;
    float* p = out + (size_t)row * EE;
    const int tid = threadIdx.x;

    float v0 = p[tid], v1 = p[tid + 256];
    float s = v0 + v1;
    float q = v0 * v0 + v1 * v1;
    #pragma unroll
    for (int off = 16; off > 0; off >>= 1) {
        s += __shfl_xor_sync(0xffffffffu, s, off);
        q += __shfl_xor_sync(0xffffffffu, q, off);
    }
    const int wid = tid >> 5, lid = tid & 31;
    if (lid == 0) { red[wid] = s; red[8 + wid] = q; }
    __syncthreads();
    s = 0.0f; q = 0.0f;
    #pragma unroll
    for (int w = 0; w < 8; w++) { s += red[w]; q += red[8 + w]; }

    float mu = s * (1.0f / EE);
    float var = q * (1.0f / EE) - mu * mu;
    float inv = rsqrtf(var + 1e-5f);
    p[tid]       = (v0 - mu) * inv * gamma[tid]       + beta[tid];
    p[tid + 256] = (v1 - mu) * inv * gamma[tid + 256] + beta[tid + 256];
}

// ---------------------------------------------------------------------------
extern "C" void kernel_launch(void* const* d_in, const int* in_sizes, int n_in,
                              void* d_out, int out_size)
{
    const float* x     = (const float*)d_in[0];
    const float* Wq    = (const float*)d_in[1];
    const float* Wk    = (const float*)d_in[2];
    const float* Wv    = (const float*)d_in[3];
    const float* Er    = (const float*)d_in[4];
    const float* gamma = (const float*)d_in[5];
    const float* beta  = (const float*)d_in[6];
    float* out = (float*)d_out;

    cudaFuncSetAttribute(attn_kernel,
                         cudaFuncAttributeMaxDynamicSharedMemorySize, SMEM_BYTES);

    qkv_kernel<<<dim3(EE / 64, (BB * SS) / 64, 3), 256>>>(x, Wq, Wk, Wv);
    attn_kernel<<<dim3(SS / 64, BB * HH), 256, SMEM_BYTES>>>(Er, out);
    ln_kernel<<<BB * SS, 256>>>(out, gamma, beta);
}

// round 2
// speedup vs baseline: 1.6764x; 1.6764x over previous
#include <cuda_runtime.h>
#include <math.h>

#define BB 4
#define SS 2048
#define EE 512
#define HH 8
#define HD 64
#define SCALE 0.04419417382415922f  /* 512^-0.5 (reference scales by E, not HD) */

// Scratch (static device arrays — allocation rules forbid cudaMalloc)
__device__ float g_q[BB * HH * SS * HD];
__device__ float g_k[BB * HH * SS * HD];
__device__ float g_v[BB * HH * SS * HD];

// ---------------------------------------------------------------------------
// Kernel 1: fused QKV projection (unchanged from R1 — SIMT, 430us; next target)
// ---------------------------------------------------------------------------
__global__ void __launch_bounds__(256) qkv_kernel(
    const float* __restrict__ x,
    const float* __restrict__ Wq,
    const float* __restrict__ Wk,
    const float* __restrict__ Wv)
{
    const float* W = blockIdx.z == 0 ? Wq : (blockIdx.z == 1 ? Wk : Wv);
    float* out = blockIdx.z == 0 ? g_q : (blockIdx.z == 1 ? g_k : g_v);
    const int m0 = blockIdx.y * 64;
    const int n0 = blockIdx.x * 64;

    __shared__ float As[32][65];
    __shared__ float Bs[32][65];

    const int tid = threadIdx.x;
    const int ty = tid >> 4, tx = tid & 15;

    float acc[4][4] = {};

    for (int k0 = 0; k0 < EE; k0 += 32) {
        #pragma unroll
        for (int t = tid; t < 2048; t += 256) {
            int i = t >> 5, k = t & 31;
            As[k][i] = x[(size_t)(m0 + i) * EE + k0 + k];
            Bs[k][i] = W[(size_t)(n0 + i) * EE + k0 + k];
        }
        __syncthreads();
        #pragma unroll 8
        for (int k = 0; k < 32; k++) {
            float a[4], b[4];
            #pragma unroll
            for (int u = 0; u < 4; u++) { a[u] = As[k][ty * 4 + u]; b[u] = Bs[k][tx * 4 + u]; }
            #pragma unroll
            for (int u = 0; u < 4; u++)
                #pragma unroll
                for (int v = 0; v < 4; v++)
                    acc[u][v] += a[u] * b[v];
        }
        __syncthreads();
    }

    #pragma unroll
    for (int u = 0; u < 4; u++) {
        int m = m0 + ty * 4 + u;
        int b_ = m / SS, s_ = m % SS;
        #pragma unroll
        for (int v = 0; v < 4; v++) {
            int n = n0 + tx * 4 + v;
            int h = n / HD, d = n & (HD - 1);
            out[(((size_t)b_ * HH + h) * SS + s_) * HD + d] = acc[u][v];
        }
    }
}

// ---------------------------------------------------------------------------
// Kernel 2: flash attention with relative-position skew — mma.sync TF32.
//
// Srel[i,j] = q_i . Er[S-1-(i-j)]  (j<=i) | 0 (j=i+1) | q_{i+1} . Er[j-i-2] (j>=i+2)
//
// Per CTA: 128 query rows, 8 warps x 16 rows. Per 64-key tile:
//   S   = Q K^T            (tf32 mma, A-frags resident in regs)
//   R1  = Q  W1window      (tf32 mma, per-warp 16x80, gather tl = jj+15-rr)
//   R2  = Q+1 W2window     (tf32 mma, A-frags shifted one row; same gather)
//   O  += P V              (3-pass split tf32: ah*bh + ah*bl + al*bh)
// ---------------------------------------------------------------------------
#define QP 68
#define KP 72
#define VP 72
#define WP 200
#define RP 84
#define SM_Q  0
#define SM_K  (129 * QP)            /* 8772  */
#define SM_V  (SM_K + 64 * KP)      /* 13380 */
#define SM_W1 (SM_V + 64 * VP)      /* 17988 */
#define SM_W2 (SM_W1 + 64 * WP)     /* 30788 */
#define SM_R  (SM_W2 + 64 * WP)     /* 43588 */
#define SM_TOT_FLOATS (SM_R + 128 * RP)  /* 54340 */
#define SMEM_BYTES (SM_TOT_FLOATS * 4)

__device__ __forceinline__ unsigned f2tf(float x) {
    unsigned r;
    asm("cvt.rna.tf32.f32 %0, %1;" : "=r"(r) : "f"(x));
    return r;
}

__device__ __forceinline__ void mma8(float4& c,
    unsigned a0, unsigned a1, unsigned a2, unsigned a3,
    unsigned b0, unsigned b1)
{
    asm("mma.sync.aligned.m16n8k8.row.col.f32.tf32.tf32.f32 "
        "{%0,%1,%2,%3}, {%4,%5,%6,%7}, {%8,%9}, {%0,%1,%2,%3};"
        : "+f"(c.x), "+f"(c.y), "+f"(c.z), "+f"(c.w)
        : "r"(a0), "r"(a1), "r"(a2), "r"(a3), "r"(b0), "r"(b1));
}

__global__ void __launch_bounds__(256, 1) attn_kernel(
    const float* __restrict__ Er, float* __restrict__ out)
{
    extern __shared__ float sm[];
    float* Qs  = sm + SM_Q;    // [129][QP]  fp32 Q rows (row 128 = q_{i0+128}); aliased by P after frag build
    float* Ks  = sm + SM_K;    // [64][KP]   tf32 K^T  [d][j]
    float* Vs  = sm + SM_V;    // [64][VP]   fp32 V    [j][d]
    float* W1  = sm + SM_W1;   // [64][WP]   tf32 Er window, case 1
    float* W2  = sm + SM_W2;   // [64][WP]   tf32 Er window, case 2
    float* Rscr= sm + SM_R;    // [128][RP]  per-warp R scratch (fp32)
    float* Pbuf = Qs;          // alias

    const int tid  = threadIdx.x;
    const int lane = tid & 31;
    const int warp = tid >> 5;
    const int g = lane >> 2;     // 0..7
    const int t = lane & 3;      // 0..3
    const int rbase = warp * 16;

    const int bh = blockIdx.y;
    const int i0 = blockIdx.x * 128;

    const float* qb0 = g_q + (size_t)bh * SS * HD;
    const float* kb0 = g_k + (size_t)bh * SS * HD;
    const float* vb0 = g_v + (size_t)bh * SS * HD;

    // ---- stage Q rows i0..i0+128 (row 128 zero-padded past S) ----
    for (int idx = tid; idx < 129 * 16; idx += 256) {
        int r = idx >> 4, dq = (idx & 15) * 4;
        float4 v = make_float4(0.f, 0.f, 0.f, 0.f);
        int gi = i0 + r;
        if (gi < SS) v = *(const float4*)&qb0[(size_t)gi * HD + dq];
        *(float4*)&Qs[r * QP + dq] = v;
    }
    __syncthreads();

    // ---- build resident A fragments (tf32) ----
    unsigned aq[8][4], aq2[8][4];
    {
        const float* r0 = &Qs[(rbase + g) * QP];
        const float* r1 = &Qs[(rbase + g + 8) * QP];
        const float* s0 = &Qs[(rbase + g + 1) * QP];
        const float* s1 = &Qs[(rbase + g + 9) * QP];
        #pragma unroll
        for (int s = 0; s < 8; s++) {
            aq[s][0]  = f2tf(r0[8 * s + t]);
            aq[s][1]  = f2tf(r1[8 * s + t]);
            aq[s][2]  = f2tf(r0[8 * s + t + 4]);
            aq[s][3]  = f2tf(r1[8 * s + t + 4]);
            aq2[s][0] = f2tf(s0[8 * s + t]);
            aq2[s][1] = f2tf(s1[8 * s + t]);
            aq2[s][2] = f2tf(s0[8 * s + t + 4]);
            aq2[s][3] = f2tf(s1[8 * s + t + 4]);
        }
    }

    float4 Oacc[8];
    #pragma unroll
    for (int n = 0; n < 8; n++) Oacc[n] = make_float4(0.f, 0.f, 0.f, 0.f);
    float m0r = -1e30f, m1r = -1e30f, l0r = 0.f, l1r = 0.f;

    const float* rp0 = &Rscr[(rbase + g) * RP];
    const float* rp1 = &Rscr[(rbase + g + 8) * RP];
    float* wr0 = &Rscr[(rbase + g) * RP + 2 * t];
    float* wr1 = &Rscr[(rbase + g + 8) * RP + 2 * t];
    const int off1w = 112 - rbase;
    const int tlb = 2 * t + 15 - g;                    // gather base (row0, n=0, e=0)
    const int diffb = (2 * t) - (i0 + rbase + g);      // + j0 + 8n per tile

    for (int j0 = 0; j0 < SS; j0 += 64) {
        __syncthreads();  // previous PV / gathers done before restaging

        const bool need1 = (j0 <= i0 + 127);
        const bool need2 = (j0 + 63 >= i0 + 2);
        const int L1 = SS - 128 - i0 + j0;
        const int L2 = j0 - i0 - 129;

        // ---- stage K^T (tf32), V (fp32) ----
        for (int idx = tid; idx < 64 * 16; idx += 256) {
            int j = idx >> 4, dq = (idx & 15) * 4;
            float4 kv = *(const float4*)&kb0[(size_t)(j0 + j) * HD + dq];
            Ks[(dq + 0) * KP + j] = __uint_as_float(f2tf(kv.x));
            Ks[(dq + 1) * KP + j] = __uint_as_float(f2tf(kv.y));
            Ks[(dq + 2) * KP + j] = __uint_as_float(f2tf(kv.z));
            Ks[(dq + 3) * KP + j] = __uint_as_float(f2tf(kv.w));
            *(float4*)&Vs[j * VP + dq] = *(const float4*)&vb0[(size_t)(j0 + j) * HD + dq];
        }
        // ---- stage Er windows (tf32, zero-filled) ----
        if (need1) {
            for (int idx = tid; idx < 192 * 16; idx += 256) {
                int tl = idx >> 4, dq = (idx & 15) * 4;
                int l = L1 + tl;
                float4 e = make_float4(0.f, 0.f, 0.f, 0.f);
                if (l >= 0 && l < SS) e = *(const float4*)&Er[(size_t)l * HD + dq];
                W1[(dq + 0) * WP + tl] = __uint_as_float(f2tf(e.x));
                W1[(dq + 1) * WP + tl] = __uint_as_float(f2tf(e.y));
                W1[(dq + 2) * WP + tl] = __uint_as_float(f2tf(e.z));
                W1[(dq + 3) * WP + tl] = __uint_as_float(f2tf(e.w));
            }
        }
        if (need2) {
            for (int idx = tid; idx < 192 * 16; idx += 256) {
                int tl = idx >> 4, dq = (idx & 15) * 4;
                int l = L2 + tl;
                float4 e = make_float4(0.f, 0.f, 0.f, 0.f);
                if (l >= 0 && l < SS) e = *(const float4*)&Er[(size_t)l * HD + dq];
                W2[(dq + 0) * WP + tl] = __uint_as_float(f2tf(e.x));
                W2[(dq + 1) * WP + tl] = __uint_as_float(f2tf(e.y));
                W2[(dq + 2) * WP + tl] = __uint_as_float(f2tf(e.z));
                W2[(dq + 3) * WP + tl] = __uint_as_float(f2tf(e.w));
            }
        }
        __syncthreads();

        // ---- S = Q K^T ----
        float4 sacc[8];
        #pragma unroll
        for (int n = 0; n < 8; n++) {
            float4 c = make_float4(0.f, 0.f, 0.f, 0.f);
            #pragma unroll
            for (int s = 0; s < 8; s++) {
                unsigned b0 = __float_as_uint(Ks[(8 * s + t) * KP + 8 * n + g]);
                unsigned b1 = __float_as_uint(Ks[(8 * s + t + 4) * KP + 8 * n + g]);
                mma8(c, aq[s][0], aq[s][1], aq[s][2], aq[s][3], b0, b1);
            }
            sacc[n] = c;
        }

        const bool wneed1 = (j0 <= i0 + rbase + 15);
        const bool wneed2 = (j0 + 63 >= i0 + rbase + 2);

        // ---- case-1 relative term ----
        if (wneed1) {
            #pragma unroll
            for (int n = 0; n < 10; n++) {
                float4 c = make_float4(0.f, 0.f, 0.f, 0.f);
                #pragma unroll
                for (int s = 0; s < 8; s++) {
                    unsigned b0 = __float_as_uint(W1[(8 * s + t) * WP + off1w + 8 * n + g]);
                    unsigned b1 = __float_as_uint(W1[(8 * s + t + 4) * WP + off1w + 8 * n + g]);
                    mma8(c, aq[s][0], aq[s][1], aq[s][2], aq[s][3], b0, b1);
                }
                wr0[8 * n] = c.x; wr0[8 * n + 1] = c.y;
                wr1[8 * n] = c.z; wr1[8 * n + 1] = c.w;
            }
            __syncwarp();
            #pragma unroll
            for (int n = 0; n < 8; n++) {
                int d00 = diffb + j0 + 8 * n;
                int tl = tlb + 8 * n;
                if (d00 <= 0)     sacc[n].x += rp0[tl];
                if (d00 + 1 <= 0) sacc[n].y += rp0[tl + 1];
                if (d00 - 8 <= 0) sacc[n].z += rp1[tl - 8];
                if (d00 - 7 <= 0) sacc[n].w += rp1[tl - 7];
            }
            __syncwarp();
        }
        // ---- case-2 relative term (shifted-row A frags, same gather) ----
        if (wneed2) {
            #pragma unroll
            for (int n = 0; n < 10; n++) {
                float4 c = make_float4(0.f, 0.f, 0.f, 0.f);
                #pragma unroll
                for (int s = 0; s < 8; s++) {
                    unsigned b0 = __float_as_uint(W2[(8 * s + t) * WP + off1w + 8 * n + g]);
                    unsigned b1 = __float_as_uint(W2[(8 * s + t + 4) * WP + off1w + 8 * n + g]);
                    mma8(c, aq2[s][0], aq2[s][1], aq2[s][2], aq2[s][3], b0, b1);
                }
                wr0[8 * n] = c.x; wr0[8 * n + 1] = c.y;
                wr1[8 * n] = c.z; wr1[8 * n + 1] = c.w;
            }
            __syncwarp();
            #pragma unroll
            for (int n = 0; n < 8; n++) {
                int d00 = diffb + j0 + 8 * n;
                int tl = tlb + 8 * n;
                if (d00 >= 2)     sacc[n].x += rp0[tl];
                if (d00 + 1 >= 2) sacc[n].y += rp0[tl + 1];
                if (d00 - 8 >= 2) sacc[n].z += rp1[tl - 8];
                if (d00 - 7 >= 2) sacc[n].w += rp1[tl - 7];
            }
            __syncwarp();
        }

        // ---- scale + online softmax ----
        float mx0 = -1e30f, mx1 = -1e30f;
        #pragma unroll
        for (int n = 0; n < 8; n++) {
            sacc[n].x *= SCALE; sacc[n].y *= SCALE;
            sacc[n].z *= SCALE; sacc[n].w *= SCALE;
            mx0 = fmaxf(mx0, fmaxf(sacc[n].x, sacc[n].y));
            mx1 = fmaxf(mx1, fmaxf(sacc[n].z, sacc[n].w));
        }
        #pragma unroll
        for (int off = 1; off <= 2; off <<= 1) {
            mx0 = fmaxf(mx0, __shfl_xor_sync(0xffffffffu, mx0, off));
            mx1 = fmaxf(mx1, __shfl_xor_sync(0xffffffffu, mx1, off));
        }
        float mn0 = fmaxf(m0r, mx0), mn1 = fmaxf(m1r, mx1);
        float c0 = __expf(m0r - mn0), c1 = __expf(m1r - mn1);
        float rs0 = 0.f, rs1 = 0.f;
        #pragma unroll
        for (int n = 0; n < 8; n++) {
            sacc[n].x = __expf(sacc[n].x - mn0);
            sacc[n].y = __expf(sacc[n].y - mn0);
            sacc[n].z = __expf(sacc[n].z - mn1);
            sacc[n].w = __expf(sacc[n].w - mn1);
            rs0 += sacc[n].x + sacc[n].y;
            rs1 += sacc[n].z + sacc[n].w;
        }
        #pragma unroll
        for (int off = 1; off <= 2; off <<= 1) {
            rs0 += __shfl_xor_sync(0xffffffffu, rs0, off);
            rs1 += __shfl_xor_sync(0xffffffffu, rs1, off);
        }
        l0r = l0r * c0 + rs0;  m0r = mn0;
        l1r = l1r * c1 + rs1;  m1r = mn1;
        #pragma unroll
        for (int n = 0; n < 8; n++) {
            Oacc[n].x *= c0; Oacc[n].y *= c0;
            Oacc[n].z *= c1; Oacc[n].w *= c1;
        }

        // ---- stage P (warp-private rows) ----
        #pragma unroll
        for (int n = 0; n < 8; n++) {
            *(float2*)&Pbuf[(rbase + g) * QP + 8 * n + 2 * t]     = make_float2(sacc[n].x, sacc[n].y);
            *(float2*)&Pbuf[(rbase + g + 8) * QP + 8 * n + 2 * t] = make_float2(sacc[n].z, sacc[n].w);
        }
        __syncwarp();

        // ---- O += P V  (3-pass split tf32) ----
        #pragma unroll
        for (int s = 0; s < 8; s++) {
            float p0 = Pbuf[(rbase + g) * QP + 8 * s + t];
            float p1 = Pbuf[(rbase + g + 8) * QP + 8 * s + t];
            float p2 = Pbuf[(rbase + g) * QP + 8 * s + t + 4];
            float p3 = Pbuf[(rbase + g + 8) * QP + 8 * s + t + 4];
            unsigned ah0 = f2tf(p0), ah1 = f2tf(p1), ah2 = f2tf(p2), ah3 = f2tf(p3);
            unsigned al0 = f2tf(p0 - __uint_as_float(ah0));
            unsigned al1 = f2tf(p1 - __uint_as_float(ah1));
            unsigned al2 = f2tf(p2 - __uint_as_float(ah2));
            unsigned al3 = f2tf(p3 - __uint_as_float(ah3));
            #pragma unroll
            for (int n = 0; n < 8; n++) {
                float v0 = Vs[(8 * s + t) * VP + 8 * n + g];
                float v1 = Vs[(8 * s + t + 4) * VP + 8 * n + g];
                unsigned bh0 = f2tf(v0), bh1 = f2tf(v1);
                unsigned bl0 = f2tf(v0 - __uint_as_float(bh0));
                unsigned bl1 = f2tf(v1 - __uint_as_float(bh1));
                mma8(Oacc[n], ah0, ah1, ah2, ah3, bh0, bh1);
                mma8(Oacc[n], ah0, ah1, ah2, ah3, bl0, bl1);
                mma8(Oacc[n], al0, al1, al2, al3, bh0, bh1);
            }
        }
    }

    // ---- normalize + write out [b][s][h*64+d] ----
    const int b_ = bh >> 3, h = bh & 7;
    const float inv0 = 1.0f / l0r, inv1 = 1.0f / l1r;
    float* op0 = out + ((size_t)b_ * SS + (i0 + rbase + g)) * EE + h * HD;
    float* op1 = out + ((size_t)b_ * SS + (i0 + rbase + g + 8)) * EE + h * HD;
    #pragma unroll
    for (int n = 0; n < 8; n++) {
        *(float2*)&op0[8 * n + 2 * t] = make_float2(Oacc[n].x * inv0, Oacc[n].y * inv0);
        *(float2*)&op1[8 * n + 2 * t] = make_float2(Oacc[n].z * inv1, Oacc[n].w * inv1);
    }
}

// ---------------------------------------------------------------------------
// Kernel 3: in-place LayerNorm over E=512 per (b,s) row (unchanged).
// ---------------------------------------------------------------------------
__global__ void __launch_bounds__(256) ln_kernel(
    float* __restrict__ out,
    const float* __restrict__ gamma,
    const float* __restrict__ beta)
{
    __shared__ float red[16];
    const int row = blockIdx.x;
    float* p = out + (size_t)row * EE;
    const int tid = threadIdx.x;

    float v0 = p[tid], v1 = p[tid + 256];
    float s = v0 + v1;
    float q = v0 * v0 + v1 * v1;
    #pragma unroll
    for (int off = 16; off > 0; off >>= 1) {
        s += __shfl_xor_sync(0xffffffffu, s, off);
        q += __shfl_xor_sync(0xffffffffu, q, off);
    }
    const int wid = tid >> 5, lid = tid & 31;
    if (lid == 0) { red[wid] = s; red[8 + wid] = q; }
    __syncthreads();
    s = 0.0f; q = 0.0f;
    #pragma unroll
    for (int w = 0; w < 8; w++) { s += red[w]; q += red[8 + w]; }

    float mu = s * (1.0f / EE);
    float var = q * (1.0f / EE) - mu * mu;
    float inv = rsqrtf(var + 1e-5f);
    p[tid]       = (v0 - mu) * inv * gamma[tid]       + beta[tid];
    p[tid + 256] = (v1 - mu) * inv * gamma[tid + 256] + beta[tid + 256];
}

// ---------------------------------------------------------------------------
extern "C" void kernel_launch(void* const* d_in, const int* in_sizes, int n_in,
                              void* d_out, int out_size)
{
    const float* x     = (const float*)d_in[0];
    const float* Wq    = (const float*)d_in[1];
    const float* Wk    = (const float*)d_in[2];
    const float* Wv    = (const float*)d_in[3];
    const float* Er    = (const float*)d_in[4];
    const float* gamma = (const float*)d_in[5];
    const float* beta  = (const float*)d_in[6];
    float* out = (float*)d_out;

    cudaFuncSetAttribute(attn_kernel,
                         cudaFuncAttributeMaxDynamicSharedMemorySize, SMEM_BYTES);

    qkv_kernel<<<dim3(EE / 64, (BB * SS) / 64, 3), 256>>>(x, Wq, Wk, Wv);
    attn_kernel<<<dim3(SS / 128, BB * HH), 256, SMEM_BYTES>>>(Er, out);
    ln_kernel<<<BB * SS, 256>>>(out, gamma, beta);
}

// round 3
// speedup vs baseline: 2.1407x; 1.2770x over previous
#include <cuda_runtime.h>
#include <math.h>

#define BB 4
#define SS 2048
#define EE 512
#define HH 8
#define HD 64
#define SCALE 0.04419417382415922f  /* 512^-0.5 (reference scales by E, not HD) */

// Scratch (static device arrays — allocation rules forbid cudaMalloc)
__device__ float g_q[BB * HH * SS * HD];
__device__ float g_k[BB * HH * SS * HD];
__device__ float g_v[BB * HH * SS * HD];

// ---------------------------------------------------------------------------
// helpers
// ---------------------------------------------------------------------------
__device__ __forceinline__ unsigned f2tf(float x) {
    unsigned r;
    asm("cvt.rna.tf32.f32 %0, %1;" : "=r"(r) : "f"(x));
    return r;
}
// pack {upper=hi, lower=lo} bf16x2
__device__ __forceinline__ unsigned pk2(float hi, float lo) {
    unsigned r;
    asm("cvt.rn.bf16x2.f32 %0, %1, %2;" : "=r"(r) : "f"(hi), "f"(lo));
    return r;
}
__device__ __forceinline__ float lo16f(unsigned u) { return __uint_as_float(u << 16); }
__device__ __forceinline__ float hi16f(unsigned u) { return __uint_as_float(u & 0xffff0000u); }

__device__ __forceinline__ void mma8(float4& c,
    unsigned a0, unsigned a1, unsigned a2, unsigned a3,
    unsigned b0, unsigned b1)
{
    asm("mma.sync.aligned.m16n8k8.row.col.f32.tf32.tf32.f32 "
        "{%0,%1,%2,%3}, {%4,%5,%6,%7}, {%8,%9}, {%0,%1,%2,%3};"
        : "+f"(c.x), "+f"(c.y), "+f"(c.z), "+f"(c.w)
        : "r"(a0), "r"(a1), "r"(a2), "r"(a3), "r"(b0), "r"(b1));
}
__device__ __forceinline__ void mma16(float4& c,
    unsigned a0, unsigned a1, unsigned a2, unsigned a3,
    unsigned b0, unsigned b1)
{
    asm("mma.sync.aligned.m16n8k16.row.col.f32.bf16.bf16.f32 "
        "{%0,%1,%2,%3}, {%4,%5,%6,%7}, {%8,%9}, {%0,%1,%2,%3};"
        : "+f"(c.x), "+f"(c.y), "+f"(c.z), "+f"(c.w)
        : "r"(a0), "r"(a1), "r"(a2), "r"(a3), "r"(b0), "r"(b1));
}
__device__ __forceinline__ void cpa16(float* dst, const float* src) {
    unsigned sa = (unsigned)__cvta_generic_to_shared(dst);
    asm volatile("cp.async.cg.shared.global [%0], [%1], 16;" :: "r"(sa), "l"(src));
}
#define CP_COMMIT() asm volatile("cp.async.commit_group;")
#define CP_WAIT(n)  asm volatile("cp.async.wait_group %0;" :: "n"(n))

// ---------------------------------------------------------------------------
// Kernel 1: QKV projection via mma.sync.
//   z=0/1 (Q/K): tf32 single-pass.  z=2 (V): bf16 3-pass split (hi/lo).
// CTA 128m x 128n, 8 warps (2x4), warp 64x32, panel K=32 double-buffered cp.async.
// smem: X[2][128][36] @0, W[2][128][36] @9216  (73728 B)
// ---------------------------------------------------------------------------
#define QKV_SMEM_BYTES (18432 * 4)

__global__ void __launch_bounds__(256, 1) qkv_mma_kernel(
    const float* __restrict__ x,
    const float* __restrict__ Wq,
    const float* __restrict__ Wk,
    const float* __restrict__ Wv)
{
    extern __shared__ float sm[];
    const int z = blockIdx.z;
    const float* W = z == 0 ? Wq : (z == 1 ? Wk : Wv);
    float* outp = z == 0 ? g_q : (z == 1 ? g_k : g_v);
    const int m0 = blockIdx.y * 128;
    const int n0 = blockIdx.x * 128;

    const int tid = threadIdx.x;
    const int lane = tid & 31, warp = tid >> 5;
    const int g = lane >> 2, t = lane & 3;
    const int mw = (warp >> 2) * 64, nw = (warp & 3) * 32;

    float* Xs[2] = { sm, sm + 4608 };
    float* Ws[2] = { sm + 9216, sm + 13824 };

    // stage panel k0 into buffer buf
    const int r_ = tid >> 1;                 // 0..127
    const int c_ = (tid & 1) * 16;           // 0 or 16 (float4 pairs x2)
    #define STAGE(buf, k0) do { \
        cpa16(Xs[buf] + r_ * 36 + c_,      &x[(size_t)(m0 + r_) * EE + (k0) + c_]); \
        cpa16(Xs[buf] + r_ * 36 + c_ + 4,  &x[(size_t)(m0 + r_) * EE + (k0) + c_ + 4]); \
        cpa16(Xs[buf] + r_ * 36 + c_ + 8,  &x[(size_t)(m0 + r_) * EE + (k0) + c_ + 8]); \
        cpa16(Xs[buf] + r_ * 36 + c_ + 12, &x[(size_t)(m0 + r_) * EE + (k0) + c_ + 12]); \
        cpa16(Ws[buf] + r_ * 36 + c_,      &W[(size_t)(n0 + r_) * EE + (k0) + c_]); \
        cpa16(Ws[buf] + r_ * 36 + c_ + 4,  &W[(size_t)(n0 + r_) * EE + (k0) + c_ + 4]); \
        cpa16(Ws[buf] + r_ * 36 + c_ + 8,  &W[(size_t)(n0 + r_) * EE + (k0) + c_ + 8]); \
        cpa16(Ws[buf] + r_ * 36 + c_ + 12, &W[(size_t)(n0 + r_) * EE + (k0) + c_ + 12]); \
        CP_COMMIT(); \
    } while (0)

    float4 acc[4][4];
    #pragma unroll
    for (int m = 0; m < 4; m++)
        #pragma unroll
        for (int n = 0; n < 4; n++) acc[m][n] = make_float4(0.f, 0.f, 0.f, 0.f);

    STAGE(0, 0);

    for (int p = 0; p < 16; p++) {
        if (p < 15) STAGE((p + 1) & 1, (p + 1) * 32);
        if (p < 15) { CP_WAIT(1); } else { CP_WAIT(0); }
        __syncthreads();
        const float* Xb = Xs[p & 1];
        const float* Wb = Ws[p & 1];

        if (z < 2) {
            // ---- tf32 single-pass: 4 k8 steps ----
            #pragma unroll
            for (int s = 0; s < 4; s++) {
                unsigned a[4][4], b[4][2];
                #pragma unroll
                for (int m = 0; m < 4; m++) {
                    const float* r0 = &Xb[(mw + 16 * m + g) * 36 + 8 * s];
                    const float* r1 = &Xb[(mw + 16 * m + g + 8) * 36 + 8 * s];
                    a[m][0] = f2tf(r0[t]);
                    a[m][1] = f2tf(r1[t]);
                    a[m][2] = f2tf(r0[t + 4]);
                    a[m][3] = f2tf(r1[t + 4]);
                }
                #pragma unroll
                for (int n = 0; n < 4; n++) {
                    const float* w0 = &Wb[(nw + 8 * n + g) * 36 + 8 * s];
                    b[n][0] = f2tf(w0[t]);
                    b[n][1] = f2tf(w0[t + 4]);
                }
                #pragma unroll
                for (int m = 0; m < 4; m++)
                    #pragma unroll
                    for (int n = 0; n < 4; n++)
                        mma8(acc[m][n], a[m][0], a[m][1], a[m][2], a[m][3],
                             b[n][0], b[n][1]);
            }
        } else {
            // ---- bf16 3-pass split: 2 k16 steps ----
            #pragma unroll
            for (int s = 0; s < 2; s++) {
                unsigned ah[4][4], al[4][4], bh[4][2], bl[4][2];
                #pragma unroll
                for (int m = 0; m < 4; m++) {
                    const float* r0 = &Xb[(mw + 16 * m + g) * 36 + 16 * s];
                    const float* r1 = &Xb[(mw + 16 * m + g + 8) * 36 + 16 * s];
                    float2 f0 = *(const float2*)&r0[2 * t];
                    float2 f1 = *(const float2*)&r1[2 * t];
                    float2 f2 = *(const float2*)&r0[2 * t + 8];
                    float2 f3 = *(const float2*)&r1[2 * t + 8];
                    ah[m][0] = pk2(f0.y, f0.x); al[m][0] = pk2(f0.y - hi16f(ah[m][0]), f0.x - lo16f(ah[m][0]));
                    ah[m][1] = pk2(f1.y, f1.x); al[m][1] = pk2(f1.y - hi16f(ah[m][1]), f1.x - lo16f(ah[m][1]));
                    ah[m][2] = pk2(f2.y, f2.x); al[m][2] = pk2(f2.y - hi16f(ah[m][2]), f2.x - lo16f(ah[m][2]));
                    ah[m][3] = pk2(f3.y, f3.x); al[m][3] = pk2(f3.y - hi16f(ah[m][3]), f3.x - lo16f(ah[m][3]));
                }
                #pragma unroll
                for (int n = 0; n < 4; n++) {
                    const float* w0 = &Wb[(nw + 8 * n + g) * 36 + 16 * s];
                    float2 f0 = *(const float2*)&w0[2 * t];
                    float2 f1 = *(const float2*)&w0[2 * t + 8];
                    bh[n][0] = pk2(f0.y, f0.x); bl[n][0] = pk2(f0.y - hi16f(bh[n][0]), f0.x - lo16f(bh[n][0]));
                    bh[n][1] = pk2(f1.y, f1.x); bl[n][1] = pk2(f1.y - hi16f(bh[n][1]), f1.x - lo16f(bh[n][1]));
                }
                #pragma unroll
                for (int m = 0; m < 4; m++)
                    #pragma unroll
                    for (int n = 0; n < 4; n++) {
                        mma16(acc[m][n], ah[m][0], ah[m][1], ah[m][2], ah[m][3], bh[n][0], bh[n][1]);
                        mma16(acc[m][n], ah[m][0], ah[m][1], ah[m][2], ah[m][3], bl[n][0], bl[n][1]);
                        mma16(acc[m][n], al[m][0], al[m][1], al[m][2], al[m][3], bh[n][0], bh[n][1]);
                    }
            }
        }
        __syncthreads();  // compute done before this buffer is re-staged
    }

    // epilogue: write [b][h][s][d]
    #pragma unroll
    for (int m = 0; m < 4; m++) {
        int r0 = m0 + mw + 16 * m + g;
        int r1 = r0 + 8;
        int b0_ = r0 >> 11, s0_ = r0 & 2047;
        int b1_ = r1 >> 11, s1_ = r1 & 2047;
        #pragma unroll
        for (int n = 0; n < 4; n++) {
            int col = n0 + nw + 8 * n + 2 * t;
            int h = col >> 6, d = col & 63;
            *(float2*)&outp[(((size_t)b0_ * HH + h) * SS + s0_) * HD + d] =
                make_float2(acc[m][n].x, acc[m][n].y);
            *(float2*)&outp[(((size_t)b1_ * HH + h) * SS + s1_) * HD + d] =
                make_float2(acc[m][n].z, acc[m][n].w);
        }
    }
}

// ---------------------------------------------------------------------------
// Kernel 2: flash attention with relative-position skew — mma.sync.
//
// Srel[i,j] = q_i . Er[S-1-(i-j)]  (j<=i) | 0 (j=i+1) | q_{i+1} . Er[j-i-2] (j>=i+2)
//
// S, R1, R2: tf32 m16n8k8.  PV: bf16 m16n8k16 3-pass split, A-frags taken
// DIRECTLY from the softmax accumulators (layout identity), V transposed into
// packed bf16 hi/lo planes per tile.
// ---------------------------------------------------------------------------
#define QP 68
#define KP 72
#define VP 72
#define WP 200
#define RP 84
#define SM_Q  0
#define SM_K  (129 * QP)            /* 8772  */
#define SM_V  (SM_K + 64 * KP)      /* 13380 */
#define SM_W1 (SM_V + 64 * VP)      /* 17988 */
#define SM_W2 (SM_W1 + 64 * WP)     /* 30788 */
#define SM_R  (SM_W2 + 64 * WP)     /* 43588 */
#define SM_TOT_FLOATS (SM_R + 128 * RP)  /* 54340 */
#define SMEM_BYTES (SM_TOT_FLOATS * 4)

__global__ void __launch_bounds__(256, 1) attn_kernel(
    const float* __restrict__ Er, float* __restrict__ out)
{
    extern __shared__ float sm[];
    float* Qs  = sm + SM_Q;    // [129][QP] fp32 Q rows (prologue only)
    float* Ks  = sm + SM_K;    // [64][KP]  tf32 K^T [d][j]
    float* Vs  = sm + SM_V;    // [64][VP]  fp32 V   [j][d]
    float* W1  = sm + SM_W1;   // [64][WP]  tf32 Er window, case 1
    float* W2  = sm + SM_W2;   // [64][WP]  tf32 Er window, case 2
    float* Rscr= sm + SM_R;    // [128][RP] per-warp R scratch
    unsigned* Vth = (unsigned*)sm;          // [64][36] bf16x2 hi (overlays Qs)
    unsigned* Vtl = ((unsigned*)sm) + 2304; // [64][36] bf16x2 lo

    const int tid  = threadIdx.x;
    const int lane = tid & 31;
    const int warp = tid >> 5;
    const int g = lane >> 2;     // 0..7
    const int t = lane & 3;      // 0..3
    const int rbase = warp * 16;

    const int bh = blockIdx.y;
    const int i0 = blockIdx.x * 128;

    const float* qb0 = g_q + (size_t)bh * SS * HD;
    const float* kb0 = g_k + (size_t)bh * SS * HD;
    const float* vb0 = g_v + (size_t)bh * SS * HD;

    // ---- stage Q rows i0..i0+128 ----
    for (int idx = tid; idx < 129 * 16; idx += 256) {
        int r = idx >> 4, dq = (idx & 15) * 4;
        float4 v = make_float4(0.f, 0.f, 0.f, 0.f);
        int gi = i0 + r;
        if (gi < SS) v = *(const float4*)&qb0[(size_t)gi * HD + dq];
        *(float4*)&Qs[r * QP + dq] = v;
    }
    __syncthreads();

    // ---- resident A fragments (tf32) ----
    unsigned aq[8][4], aq2[8][4];
    {
        const float* r0 = &Qs[(rbase + g) * QP];
        const float* r1 = &Qs[(rbase + g + 8) * QP];
        const float* s0 = &Qs[(rbase + g + 1) * QP];
        const float* s1 = &Qs[(rbase + g + 9) * QP];
        #pragma unroll
        for (int s = 0; s < 8; s++) {
            aq[s][0]  = f2tf(r0[8 * s + t]);
            aq[s][1]  = f2tf(r1[8 * s + t]);
            aq[s][2]  = f2tf(r0[8 * s + t + 4]);
            aq[s][3]  = f2tf(r1[8 * s + t + 4]);
            aq2[s][0] = f2tf(s0[8 * s + t]);
            aq2[s][1] = f2tf(s1[8 * s + t]);
            aq2[s][2] = f2tf(s0[8 * s + t + 4]);
            aq2[s][3] = f2tf(s1[8 * s + t + 4]);
        }
    }
    __syncthreads();  // frag build done before Vth overwrites Qs

    float4 Oacc[8];
    #pragma unroll
    for (int n = 0; n < 8; n++) Oacc[n] = make_float4(0.f, 0.f, 0.f, 0.f);
    float m0r = -1e30f, m1r = -1e30f, l0r = 0.f, l1r = 0.f;

    const float* rp0 = &Rscr[(rbase + g) * RP];
    const float* rp1 = &Rscr[(rbase + g + 8) * RP];
    float* wr0 = &Rscr[(rbase + g) * RP + 2 * t];
    float* wr1 = &Rscr[(rbase + g + 8) * RP + 2 * t];
    const int off1w = 112 - rbase;
    const int tlb = 2 * t + 15 - g;
    const int diffb = (2 * t) - (i0 + rbase + g);

    for (int j0 = 0; j0 < SS; j0 += 64) {
        __syncthreads();  // previous tile compute done before restage

        const bool need1 = (j0 <= i0 + 127);
        const bool need2 = (j0 + 63 >= i0 + 2);
        const int L1 = SS - 128 - i0 + j0;
        const int L2 = j0 - i0 - 129;

        // ---- stage K^T (tf32), V (fp32) ----
        for (int idx = tid; idx < 64 * 16; idx += 256) {
            int j = idx >> 4, dq = (idx & 15) * 4;
            float4 kv = *(const float4*)&kb0[(size_t)(j0 + j) * HD + dq];
            Ks[(dq + 0) * KP + j] = __uint_as_float(f2tf(kv.x));
            Ks[(dq + 1) * KP + j] = __uint_as_float(f2tf(kv.y));
            Ks[(dq + 2) * KP + j] = __uint_as_float(f2tf(kv.z));
            Ks[(dq + 3) * KP + j] = __uint_as_float(f2tf(kv.w));
            *(float4*)&Vs[j * VP + dq] = *(const float4*)&vb0[(size_t)(j0 + j) * HD + dq];
        }
        if (need1) {
            for (int idx = tid; idx < 192 * 16; idx += 256) {
                int tl = idx >> 4, dq = (idx & 15) * 4;
                int l = L1 + tl;
                float4 e = make_float4(0.f, 0.f, 0.f, 0.f);
                if (l >= 0 && l < SS) e = *(const float4*)&Er[(size_t)l * HD + dq];
                W1[(dq + 0) * WP + tl] = __uint_as_float(f2tf(e.x));
                W1[(dq + 1) * WP + tl] = __uint_as_float(f2tf(e.y));
                W1[(dq + 2) * WP + tl] = __uint_as_float(f2tf(e.z));
                W1[(dq + 3) * WP + tl] = __uint_as_float(f2tf(e.w));
            }
        }
        if (need2) {
            for (int idx = tid; idx < 192 * 16; idx += 256) {
                int tl = idx >> 4, dq = (idx & 15) * 4;
                int l = L2 + tl;
                float4 e = make_float4(0.f, 0.f, 0.f, 0.f);
                if (l >= 0 && l < SS) e = *(const float4*)&Er[(size_t)l * HD + dq];
                W2[(dq + 0) * WP + tl] = __uint_as_float(f2tf(e.x));
                W2[(dq + 1) * WP + tl] = __uint_as_float(f2tf(e.y));
                W2[(dq + 2) * WP + tl] = __uint_as_float(f2tf(e.z));
                W2[(dq + 3) * WP + tl] = __uint_as_float(f2tf(e.w));
            }
        }
        __syncthreads();

        // ---- transpose V into packed bf16 hi/lo planes [d][jpair] ----
        #pragma unroll
        for (int ii = 0; ii < 8; ii++) {
            int idx = tid + ii * 256;
            int jp = idx >> 6, d = idx & 63;
            float v0 = Vs[(2 * jp) * VP + d];
            float v1 = Vs[(2 * jp + 1) * VP + d];
            unsigned h = pk2(v1, v0);
            unsigned l = pk2(v1 - hi16f(h), v0 - lo16f(h));
            Vth[d * 36 + jp] = h;
            Vtl[d * 36 + jp] = l;
        }
        __syncthreads();

        // ---- S = Q K^T ----
        float4 sacc[8];
        #pragma unroll
        for (int n = 0; n < 8; n++) {
            float4 c = make_float4(0.f, 0.f, 0.f, 0.f);
            #pragma unroll
            for (int s = 0; s < 8; s++) {
                unsigned b0 = __float_as_uint(Ks[(8 * s + t) * KP + 8 * n + g]);
                unsigned b1 = __float_as_uint(Ks[(8 * s + t + 4) * KP + 8 * n + g]);
                mma8(c, aq[s][0], aq[s][1], aq[s][2], aq[s][3], b0, b1);
            }
            sacc[n] = c;
        }

        const bool wneed1 = (j0 <= i0 + rbase + 15);
        const bool wneed2 = (j0 + 63 >= i0 + rbase + 2);

        // ---- case-1 relative term ----
        if (wneed1) {
            #pragma unroll
            for (int n = 0; n < 10; n++) {
                float4 c = make_float4(0.f, 0.f, 0.f, 0.f);
                #pragma unroll
                for (int s = 0; s < 8; s++) {
                    unsigned b0 = __float_as_uint(W1[(8 * s + t) * WP + off1w + 8 * n + g]);
                    unsigned b1 = __float_as_uint(W1[(8 * s + t + 4) * WP + off1w + 8 * n + g]);
                    mma8(c, aq[s][0], aq[s][1], aq[s][2], aq[s][3], b0, b1);
                }
                wr0[8 * n] = c.x; wr0[8 * n + 1] = c.y;
                wr1[8 * n] = c.z; wr1[8 * n + 1] = c.w;
            }
            __syncwarp();
            #pragma unroll
            for (int n = 0; n < 8; n++) {
                int d00 = diffb + j0 + 8 * n;
                int tl = tlb + 8 * n;
                if (d00 <= 0)     sacc[n].x += rp0[tl];
                if (d00 + 1 <= 0) sacc[n].y += rp0[tl + 1];
                if (d00 - 8 <= 0) sacc[n].z += rp1[tl - 8];
                if (d00 - 7 <= 0) sacc[n].w += rp1[tl - 7];
            }
            __syncwarp();
        }
        // ---- case-2 relative term ----
        if (wneed2) {
            #pragma unroll
            for (int n = 0; n < 10; n++) {
                float4 c = make_float4(0.f, 0.f, 0.f, 0.f);
                #pragma unroll
                for (int s = 0; s < 8; s++) {
                    unsigned b0 = __float_as_uint(W2[(8 * s + t) * WP + off1w + 8 * n + g]);
                    unsigned b1 = __float_as_uint(W2[(8 * s + t + 4) * WP + off1w + 8 * n + g]);
                    mma8(c, aq2[s][0], aq2[s][1], aq2[s][2], aq2[s][3], b0, b1);
                }
                wr0[8 * n] = c.x; wr0[8 * n + 1] = c.y;
                wr1[8 * n] = c.z; wr1[8 * n + 1] = c.w;
            }
            __syncwarp();
            #pragma unroll
            for (int n = 0; n < 8; n++) {
                int d00 = diffb + j0 + 8 * n;
                int tl = tlb + 8 * n;
                if (d00 >= 2)     sacc[n].x += rp0[tl];
                if (d00 + 1 >= 2) sacc[n].y += rp0[tl + 1];
                if (d00 - 8 >= 2) sacc[n].z += rp1[tl - 8];
                if (d00 - 7 >= 2) sacc[n].w += rp1[tl - 7];
            }
            __syncwarp();
        }

        // ---- scale + online softmax ----
        float mx0 = -1e30f, mx1 = -1e30f;
        #pragma unroll
        for (int n = 0; n < 8; n++) {
            sacc[n].x *= SCALE; sacc[n].y *= SCALE;
            sacc[n].z *= SCALE; sacc[n].w *= SCALE;
            mx0 = fmaxf(mx0, fmaxf(sacc[n].x, sacc[n].y));
            mx1 = fmaxf(mx1, fmaxf(sacc[n].z, sacc[n].w));
        }
        #pragma unroll
        for (int off = 1; off <= 2; off <<= 1) {
            mx0 = fmaxf(mx0, __shfl_xor_sync(0xffffffffu, mx0, off));
            mx1 = fmaxf(mx1, __shfl_xor_sync(0xffffffffu, mx1, off));
        }
        float mn0 = fmaxf(m0r, mx0), mn1 = fmaxf(m1r, mx1);
        float c0 = __expf(m0r - mn0), c1 = __expf(m1r - mn1);
        float rs0 = 0.f, rs1 = 0.f;
        #pragma unroll
        for (int n = 0; n < 8; n++) {
            sacc[n].x = __expf(sacc[n].x - mn0);
            sacc[n].y = __expf(sacc[n].y - mn0);
            sacc[n].z = __expf(sacc[n].z - mn1);
            sacc[n].w = __expf(sacc[n].w - mn1);
            rs0 += sacc[n].x + sacc[n].y;
            rs1 += sacc[n].z + sacc[n].w;
        }
        #pragma unroll
        for (int off = 1; off <= 2; off <<= 1) {
            rs0 += __shfl_xor_sync(0xffffffffu, rs0, off);
            rs1 += __shfl_xor_sync(0xffffffffu, rs1, off);
        }
        l0r = l0r * c0 + rs0;  m0r = mn0;
        l1r = l1r * c1 + rs1;  m1r = mn1;
        #pragma unroll
        for (int n = 0; n < 8; n++) {
            Oacc[n].x *= c0; Oacc[n].y *= c0;
            Oacc[n].z *= c1; Oacc[n].w *= c1;
        }

        // ---- O += P V  (bf16 3-pass; A-frags straight from sacc) ----
        #pragma unroll
        for (int sp = 0; sp < 4; sp++) {
            float4 pa = sacc[2 * sp], pb = sacc[2 * sp + 1];
            unsigned ah0 = pk2(pa.y, pa.x), ah1 = pk2(pa.w, pa.z);
            unsigned ah2 = pk2(pb.y, pb.x), ah3 = pk2(pb.w, pb.z);
            unsigned al0 = pk2(pa.y - hi16f(ah0), pa.x - lo16f(ah0));
            unsigned al1 = pk2(pa.w - hi16f(ah1), pa.z - lo16f(ah1));
            unsigned al2 = pk2(pb.y - hi16f(ah2), pb.x - lo16f(ah2));
            unsigned al3 = pk2(pb.w - hi16f(ah3), pb.z - lo16f(ah3));
            #pragma unroll
            for (int np = 0; np < 8; np++) {
                unsigned bh0 = Vth[(8 * np + g) * 36 + 8 * sp + t];
                unsigned bh1 = Vth[(8 * np + g) * 36 + 8 * sp + t + 4];
                unsigned bl0 = Vtl[(8 * np + g) * 36 + 8 * sp + t];
                unsigned bl1 = Vtl[(8 * np + g) * 36 + 8 * sp + t + 4];
                mma16(Oacc[np], ah0, ah1, ah2, ah3, bh0, bh1);
                mma16(Oacc[np], ah0, ah1, ah2, ah3, bl0, bl1);
                mma16(Oacc[np], al0, al1, al2, al3, bh0, bh1);
            }
        }
    }

    // ---- normalize + write out [b][s][h*64+d] ----
    const int b_ = bh >> 3, h = bh & 7;
    const float inv0 = 1.0f / l0r, inv1 = 1.0f / l1r;
    float* op0 = out + ((size_t)b_ * SS + (i0 + rbase + g)) * EE + h * HD;
    float* op1 = out + ((size_t)b_ * SS + (i0 + rbase + g + 8)) * EE + h * HD;
    #pragma unroll
    for (int n = 0; n < 8; n++) {
        *(float2*)&op0[8 * n + 2 * t] = make_float2(Oacc[n].x * inv0, Oacc[n].y * inv0);
        *(float2*)&op1[8 * n + 2 * t] = make_float2(Oacc[n].z * inv1, Oacc[n].w * inv1);
    }
}

// ---------------------------------------------------------------------------
// Kernel 3: in-place LayerNorm over E=512 per (b,s) row.
// ---------------------------------------------------------------------------
__global__ void __launch_bounds__(256) ln_kernel(
    float* __restrict__ out,
    const float* __restrict__ gamma,
    const float* __restrict__ beta)
{
    __shared__ float red[16];
    const int row = blockIdx.x;
    float* p = out + (size_t)row * EE;
    const int tid = threadIdx.x;

    float v0 = p[tid], v1 = p[tid + 256];
    float s = v0 + v1;
    float q = v0 * v0 + v1 * v1;
    #pragma unroll
    for (int off = 16; off > 0; off >>= 1) {
        s += __shfl_xor_sync(0xffffffffu, s, off);
        q += __shfl_xor_sync(0xffffffffu, q, off);
    }
    const int wid = tid >> 5, lid = tid & 31;
    if (lid == 0) { red[wid] = s; red[8 + wid] = q; }
    __syncthreads();
    s = 0.0f; q = 0.0f;
    #pragma unroll
    for (int w = 0; w < 8; w++) { s += red[w]; q += red[8 + w]; }

    float mu = s * (1.0f / EE);
    float var = q * (1.0f / EE) - mu * mu;
    float inv = rsqrtf(var + 1e-5f);
    p[tid]       = (v0 - mu) * inv * gamma[tid]       + beta[tid];
    p[tid + 256] = (v1 - mu) * inv * gamma[tid + 256] + beta[tid + 256];
}

// ---------------------------------------------------------------------------
extern "C" void kernel_launch(void* const* d_in, const int* in_sizes, int n_in,
                              void* d_out, int out_size)
{
    const float* x     = (const float*)d_in[0];
    const float* Wq    = (const float*)d_in[1];
    const float* Wk    = (const float*)d_in[2];
    const float* Wv    = (const float*)d_in[3];
    const float* Er    = (const float*)d_in[4];
    const float* gamma = (const float*)d_in[5];
    const float* beta  = (const float*)d_in[6];
    float* out = (float*)d_out;

    cudaFuncSetAttribute(qkv_mma_kernel,
                         cudaFuncAttributeMaxDynamicSharedMemorySize, QKV_SMEM_BYTES);
    cudaFuncSetAttribute(attn_kernel,
                         cudaFuncAttributeMaxDynamicSharedMemorySize, SMEM_BYTES);

    qkv_mma_kernel<<<dim3(EE / 128, (BB * SS) / 128, 3), 256, QKV_SMEM_BYTES>>>(x, Wq, Wk, Wv);
    attn_kernel<<<dim3(SS / 128, BB * HH), 256, SMEM_BYTES>>>(Er, out);
    ln_kernel<<<BB * SS, 256>>>(out, gamma, beta);
}

// round 4
// speedup vs baseline: 2.1437x; 1.0014x over previous
#include <cuda_runtime.h>
#include <math.h>

#define BB 4
#define SS 2048
#define EE 512
#define HH 8
#define HD 64
#define SCALE 0.04419417382415922f  /* 512^-0.5 (reference scales by E, not HD) */

// Scratch (static device arrays — allocation rules forbid cudaMalloc)
__device__ float g_q[BB * HH * SS * HD];
__device__ float g_k[BB * HH * SS * HD];
__device__ float g_v[BB * HH * SS * HD];

// ---------------------------------------------------------------------------
// helpers
// ---------------------------------------------------------------------------
__device__ __forceinline__ unsigned f2tf(float x) {
    unsigned r;
    asm("cvt.rna.tf32.f32 %0, %1;" : "=r"(r) : "f"(x));
    return r;
}
// pack {upper=hi, lower=lo} bf16x2
__device__ __forceinline__ unsigned pk2(float hi, float lo) {
    unsigned r;
    asm("cvt.rn.bf16x2.f32 %0, %1, %2;" : "=r"(r) : "f"(hi), "f"(lo));
    return r;
}
__device__ __forceinline__ float lo16f(unsigned u) { return __uint_as_float(u << 16); }
__device__ __forceinline__ float hi16f(unsigned u) { return __uint_as_float(u & 0xffff0000u); }

__device__ __forceinline__ void mma8(float4& c,
    unsigned a0, unsigned a1, unsigned a2, unsigned a3,
    unsigned b0, unsigned b1)
{
    asm("mma.sync.aligned.m16n8k8.row.col.f32.tf32.tf32.f32 "
        "{%0,%1,%2,%3}, {%4,%5,%6,%7}, {%8,%9}, {%0,%1,%2,%3};"
        : "+f"(c.x), "+f"(c.y), "+f"(c.z), "+f"(c.w)
        : "r"(a0), "r"(a1), "r"(a2), "r"(a3), "r"(b0), "r"(b1));
}
__device__ __forceinline__ void mma16(float4& c,
    unsigned a0, unsigned a1, unsigned a2, unsigned a3,
    unsigned b0, unsigned b1)
{
    asm("mma.sync.aligned.m16n8k16.row.col.f32.bf16.bf16.f32 "
        "{%0,%1,%2,%3}, {%4,%5,%6,%7}, {%8,%9}, {%0,%1,%2,%3};"
        : "+f"(c.x), "+f"(c.y), "+f"(c.z), "+f"(c.w)
        : "r"(a0), "r"(a1), "r"(a2), "r"(a3), "r"(b0), "r"(b1));
}
__device__ __forceinline__ void cpa16(float* dst, const float* src) {
    unsigned sa = (unsigned)__cvta_generic_to_shared(dst);
    asm volatile("cp.async.cg.shared.global [%0], [%1], 16;" :: "r"(sa), "l"(src));
}
#define CP_COMMIT() asm volatile("cp.async.commit_group;")
#define CP_WAIT(n)  asm volatile("cp.async.wait_group %0;" :: "n"(n))

// ---------------------------------------------------------------------------
// Kernel 1: QKV projection via mma.sync.
//   z=0/1 (Q/K): tf32 single-pass.  z=2 (V): bf16 3-pass split (hi/lo).
// CTA 128m x 128n, 8 warps (2x4), warp 64x32, panel K=32 double-buffered cp.async.
// smem: X[2][128][36] @0, W[2][128][36] @9216  (73728 B)
// ---------------------------------------------------------------------------
#define QKV_SMEM_BYTES (18432 * 4)

__global__ void __launch_bounds__(256, 1) qkv_mma_kernel(
    const float* __restrict__ x,
    const float* __restrict__ Wq,
    const float* __restrict__ Wk,
    const float* __restrict__ Wv)
{
    extern __shared__ float sm[];
    const int z = blockIdx.z;
    const float* W = z == 0 ? Wq : (z == 1 ? Wk : Wv);
    float* outp = z == 0 ? g_q : (z == 1 ? g_k : g_v);
    const int m0 = blockIdx.y * 128;
    const int n0 = blockIdx.x * 128;

    const int tid = threadIdx.x;
    const int lane = tid & 31, warp = tid >> 5;
    const int g = lane >> 2, t = lane & 3;
    const int mw = (warp >> 2) * 64, nw = (warp & 3) * 32;

    float* Xs[2] = { sm, sm + 4608 };
    float* Ws[2] = { sm + 9216, sm + 13824 };

    // stage panel k0 into buffer buf
    const int r_ = tid >> 1;                 // 0..127
    const int c_ = (tid & 1) * 16;           // 0 or 16 (float4 pairs x2)
    #define STAGE(buf, k0) do { \
        cpa16(Xs[buf] + r_ * 36 + c_,      &x[(size_t)(m0 + r_) * EE + (k0) + c_]); \
        cpa16(Xs[buf] + r_ * 36 + c_ + 4,  &x[(size_t)(m0 + r_) * EE + (k0) + c_ + 4]); \
        cpa16(Xs[buf] + r_ * 36 + c_ + 8,  &x[(size_t)(m0 + r_) * EE + (k0) + c_ + 8]); \
        cpa16(Xs[buf] + r_ * 36 + c_ + 12, &x[(size_t)(m0 + r_) * EE + (k0) + c_ + 12]); \
        cpa16(Ws[buf] + r_ * 36 + c_,      &W[(size_t)(n0 + r_) * EE + (k0) + c_]); \
        cpa16(Ws[buf] + r_ * 36 + c_ + 4,  &W[(size_t)(n0 + r_) * EE + (k0) + c_ + 4]); \
        cpa16(Ws[buf] + r_ * 36 + c_ + 8,  &W[(size_t)(n0 + r_) * EE + (k0) + c_ + 8]); \
        cpa16(Ws[buf] + r_ * 36 + c_ + 12, &W[(size_t)(n0 + r_) * EE + (k0) + c_ + 12]); \
        CP_COMMIT(); \
    } while (0)

    float4 acc[4][4];
    #pragma unroll
    for (int m = 0; m < 4; m++)
        #pragma unroll
        for (int n = 0; n < 4; n++) acc[m][n] = make_float4(0.f, 0.f, 0.f, 0.f);

    STAGE(0, 0);

    for (int p = 0; p < 16; p++) {
        if (p < 15) STAGE((p + 1) & 1, (p + 1) * 32);
        if (p < 15) { CP_WAIT(1); } else { CP_WAIT(0); }
        __syncthreads();
        const float* Xb = Xs[p & 1];
        const float* Wb = Ws[p & 1];

        if (z < 2) {
            // ---- tf32 single-pass: 4 k8 steps ----
            #pragma unroll
            for (int s = 0; s < 4; s++) {
                unsigned a[4][4], b[4][2];
                #pragma unroll
                for (int m = 0; m < 4; m++) {
                    const float* r0 = &Xb[(mw + 16 * m + g) * 36 + 8 * s];
                    const float* r1 = &Xb[(mw + 16 * m + g + 8) * 36 + 8 * s];
                    a[m][0] = f2tf(r0[t]);
                    a[m][1] = f2tf(r1[t]);
                    a[m][2] = f2tf(r0[t + 4]);
                    a[m][3] = f2tf(r1[t + 4]);
                }
                #pragma unroll
                for (int n = 0; n < 4; n++) {
                    const float* w0 = &Wb[(nw + 8 * n + g) * 36 + 8 * s];
                    b[n][0] = f2tf(w0[t]);
                    b[n][1] = f2tf(w0[t + 4]);
                }
                #pragma unroll
                for (int m = 0; m < 4; m++)
                    #pragma unroll
                    for (int n = 0; n < 4; n++)
                        mma8(acc[m][n], a[m][0], a[m][1], a[m][2], a[m][3],
                             b[n][0], b[n][1]);
            }
        } else {
            // ---- bf16 3-pass split: 2 k16 steps ----
            #pragma unroll
            for (int s = 0; s < 2; s++) {
                unsigned ah[4][4], al[4][4], bh[4][2], bl[4][2];
                #pragma unroll
                for (int m = 0; m < 4; m++) {
                    const float* r0 = &Xb[(mw + 16 * m + g) * 36 + 16 * s];
                    const float* r1 = &Xb[(mw + 16 * m + g + 8) * 36 + 16 * s];
                    float2 f0 = *(const float2*)&r0[2 * t];
                    float2 f1 = *(const float2*)&r1[2 * t];
                    float2 f2 = *(const float2*)&r0[2 * t + 8];
                    float2 f3 = *(const float2*)&r1[2 * t + 8];
                    ah[m][0] = pk2(f0.y, f0.x); al[m][0] = pk2(f0.y - hi16f(ah[m][0]), f0.x - lo16f(ah[m][0]));
                    ah[m][1] = pk2(f1.y, f1.x); al[m][1] = pk2(f1.y - hi16f(ah[m][1]), f1.x - lo16f(ah[m][1]));
                    ah[m][2] = pk2(f2.y, f2.x); al[m][2] = pk2(f2.y - hi16f(ah[m][2]), f2.x - lo16f(ah[m][2]));
                    ah[m][3] = pk2(f3.y, f3.x); al[m][3] = pk2(f3.y - hi16f(ah[m][3]), f3.x - lo16f(ah[m][3]));
                }
                #pragma unroll
                for (int n = 0; n < 4; n++) {
                    const float* w0 = &Wb[(nw + 8 * n + g) * 36 + 16 * s];
                    float2 f0 = *(const float2*)&w0[2 * t];
                    float2 f1 = *(const float2*)&w0[2 * t + 8];
                    bh[n][0] = pk2(f0.y, f0.x); bl[n][0] = pk2(f0.y - hi16f(bh[n][0]), f0.x - lo16f(bh[n][0]));
                    bh[n][1] = pk2(f1.y, f1.x); bl[n][1] = pk2(f1.y - hi16f(bh[n][1]), f1.x - lo16f(bh[n][1]));
                }
                #pragma unroll
                for (int m = 0; m < 4; m++)
                    #pragma unroll
                    for (int n = 0; n < 4; n++) {
                        mma16(acc[m][n], ah[m][0], ah[m][1], ah[m][2], ah[m][3], bh[n][0], bh[n][1]);
                        mma16(acc[m][n], ah[m][0], ah[m][1], ah[m][2], ah[m][3], bl[n][0], bl[n][1]);
                        mma16(acc[m][n], al[m][0], al[m][1], al[m][2], al[m][3], bh[n][0], bh[n][1]);
                    }
            }
        }
        __syncthreads();  // compute done before this buffer is re-staged
    }

    // epilogue: write [b][h][s][d]
    #pragma unroll
    for (int m = 0; m < 4; m++) {
        int r0 = m0 + mw + 16 * m + g;
        int r1 = r0 + 8;
        int b0_ = r0 >> 11, s0_ = r0 & 2047;
        int b1_ = r1 >> 11, s1_ = r1 & 2047;
        #pragma unroll
        for (int n = 0; n < 4; n++) {
            int col = n0 + nw + 8 * n + 2 * t;
            int h = col >> 6, d = col & 63;
            *(float2*)&outp[(((size_t)b0_ * HH + h) * SS + s0_) * HD + d] =
                make_float2(acc[m][n].x, acc[m][n].y);
            *(float2*)&outp[(((size_t)b1_ * HH + h) * SS + s1_) * HD + d] =
                make_float2(acc[m][n].z, acc[m][n].w);
        }
    }
}

// ---------------------------------------------------------------------------
// Kernel 2: flash attention with relative-position skew — mma.sync.
//
// Srel[i,j] = q_i . Er[S-1-(i-j)]  (j<=i) | 0 (j=i+1) | q_{i+1} . Er[j-i-2] (j>=i+2)
//
// S, R1, R2: tf32 m16n8k8.  PV: bf16 m16n8k16 3-pass split, A-frags taken
// DIRECTLY from the softmax accumulators (layout identity), V transposed into
// packed bf16 hi/lo planes per tile.
// ---------------------------------------------------------------------------
#define QP 68
#define KP 72
#define VP 72
#define WP 200
#define RP 84
#define SM_Q  0
#define SM_K  (129 * QP)            /* 8772  */
#define SM_V  (SM_K + 64 * KP)      /* 13380 */
#define SM_W1 (SM_V + 64 * VP)      /* 17988 */
#define SM_W2 (SM_W1 + 64 * WP)     /* 30788 */
#define SM_R  (SM_W2 + 64 * WP)     /* 43588 */
#define SM_TOT_FLOATS (SM_R + 128 * RP)  /* 54340 */
#define SMEM_BYTES (SM_TOT_FLOATS * 4)

__global__ void __launch_bounds__(256, 1) attn_kernel(
    const float* __restrict__ Er, float* __restrict__ out)
{
    extern __shared__ float sm[];
    float* Qs  = sm + SM_Q;    // [129][QP] fp32 Q rows (prologue only)
    float* Ks  = sm + SM_K;    // [64][KP]  tf32 K^T [d][j]
    float* Vs  = sm + SM_V;    // [64][VP]  fp32 V   [j][d]
    float* W1  = sm + SM_W1;   // [64][WP]  tf32 Er window, case 1
    float* W2  = sm + SM_W2;   // [64][WP]  tf32 Er window, case 2
    float* Rscr= sm + SM_R;    // [128][RP] per-warp R scratch
    unsigned* Vth = (unsigned*)sm;          // [64][36] bf16x2 hi (overlays Qs)
    unsigned* Vtl = ((unsigned*)sm) + 2304; // [64][36] bf16x2 lo

    const int tid  = threadIdx.x;
    const int lane = tid & 31;
    const int warp = tid >> 5;
    const int g = lane >> 2;     // 0..7
    const int t = lane & 3;      // 0..3
    const int rbase = warp * 16;

    const int bh = blockIdx.y;
    const int i0 = blockIdx.x * 128;

    const float* qb0 = g_q + (size_t)bh * SS * HD;
    const float* kb0 = g_k + (size_t)bh * SS * HD;
    const float* vb0 = g_v + (size_t)bh * SS * HD;

    // ---- stage Q rows i0..i0+128 ----
    for (int idx = tid; idx < 129 * 16; idx += 256) {
        int r = idx >> 4, dq = (idx & 15) * 4;
        float4 v = make_float4(0.f, 0.f, 0.f, 0.f);
        int gi = i0 + r;
        if (gi < SS) v = *(const float4*)&qb0[(size_t)gi * HD + dq];
        *(float4*)&Qs[r * QP + dq] = v;
    }
    __syncthreads();

    // ---- resident A fragments (tf32) ----
    unsigned aq[8][4], aq2[8][4];
    {
        const float* r0 = &Qs[(rbase + g) * QP];
        const float* r1 = &Qs[(rbase + g + 8) * QP];
        const float* s0 = &Qs[(rbase + g + 1) * QP];
        const float* s1 = &Qs[(rbase + g + 9) * QP];
        #pragma unroll
        for (int s = 0; s < 8; s++) {
            aq[s][0]  = f2tf(r0[8 * s + t]);
            aq[s][1]  = f2tf(r1[8 * s + t]);
            aq[s][2]  = f2tf(r0[8 * s + t + 4]);
            aq[s][3]  = f2tf(r1[8 * s + t + 4]);
            aq2[s][0] = f2tf(s0[8 * s + t]);
            aq2[s][1] = f2tf(s1[8 * s + t]);
            aq2[s][2] = f2tf(s0[8 * s + t + 4]);
            aq2[s][3] = f2tf(s1[8 * s + t + 4]);
        }
    }
    __syncthreads();  // frag build done before Vth overwrites Qs

    float4 Oacc[8];
    #pragma unroll
    for (int n = 0; n < 8; n++) Oacc[n] = make_float4(0.f, 0.f, 0.f, 0.f);
    float m0r = -1e30f, m1r = -1e30f, l0r = 0.f, l1r = 0.f;

    const float* rp0 = &Rscr[(rbase + g) * RP];
    const float* rp1 = &Rscr[(rbase + g + 8) * RP];
    float* wr0 = &Rscr[(rbase + g) * RP + 2 * t];
    float* wr1 = &Rscr[(rbase + g + 8) * RP + 2 * t];
    const int off1w = 112 - rbase;
    const int tlb = 2 * t + 15 - g;
    const int diffb = (2 * t) - (i0 + rbase + g);

    for (int j0 = 0; j0 < SS; j0 += 64) {
        __syncthreads();  // previous tile compute done before restage

        const bool need1 = (j0 <= i0 + 127);
        const bool need2 = (j0 + 63 >= i0 + 2);
        const int L1 = SS - 128 - i0 + j0;
        const int L2 = j0 - i0 - 129;

        // ---- stage K^T (tf32), V (fp32) ----
        for (int idx = tid; idx < 64 * 16; idx += 256) {
            int j = idx >> 4, dq = (idx & 15) * 4;
            float4 kv = *(const float4*)&kb0[(size_t)(j0 + j) * HD + dq];
            Ks[(dq + 0) * KP + j] = __uint_as_float(f2tf(kv.x));
            Ks[(dq + 1) * KP + j] = __uint_as_float(f2tf(kv.y));
            Ks[(dq + 2) * KP + j] = __uint_as_float(f2tf(kv.z));
            Ks[(dq + 3) * KP + j] = __uint_as_float(f2tf(kv.w));
            *(float4*)&Vs[j * VP + dq] = *(const float4*)&vb0[(size_t)(j0 + j) * HD + dq];
        }
        if (need1) {
            for (int idx = tid; idx < 192 * 16; idx += 256) {
                int tl = idx >> 4, dq = (idx & 15) * 4;
                int l = L1 + tl;
                float4 e = make_float4(0.f, 0.f, 0.f, 0.f);
                if (l >= 0 && l < SS) e = *(const float4*)&Er[(size_t)l * HD + dq];
                W1[(dq + 0) * WP + tl] = __uint_as_float(f2tf(e.x));
                W1[(dq + 1) * WP + tl] = __uint_as_float(f2tf(e.y));
                W1[(dq + 2) * WP + tl] = __uint_as_float(f2tf(e.z));
                W1[(dq + 3) * WP + tl] = __uint_as_float(f2tf(e.w));
            }
        }
        if (need2) {
            for (int idx = tid; idx < 192 * 16; idx += 256) {
                int tl = idx >> 4, dq = (idx & 15) * 4;
                int l = L2 + tl;
                float4 e = make_float4(0.f, 0.f, 0.f, 0.f);
                if (l >= 0 && l < SS) e = *(const float4*)&Er[(size_t)l * HD + dq];
                W2[(dq + 0) * WP + tl] = __uint_as_float(f2tf(e.x));
                W2[(dq + 1) * WP + tl] = __uint_as_float(f2tf(e.y));
                W2[(dq + 2) * WP + tl] = __uint_as_float(f2tf(e.z));
                W2[(dq + 3) * WP + tl] = __uint_as_float(f2tf(e.w));
            }
        }
        __syncthreads();

        // ---- transpose V into packed bf16 hi/lo planes [d][jpair] ----
        #pragma unroll
        for (int ii = 0; ii < 8; ii++) {
            int idx = tid + ii * 256;
            int jp = idx >> 6, d = idx & 63;
            float v0 = Vs[(2 * jp) * VP + d];
            float v1 = Vs[(2 * jp + 1) * VP + d];
            unsigned h = pk2(v1, v0);
            unsigned l = pk2(v1 - hi16f(h), v0 - lo16f(h));
            Vth[d * 36 + jp] = h;
            Vtl[d * 36 + jp] = l;
        }
        __syncthreads();

        // ---- S = Q K^T ----
        float4 sacc[8];
        #pragma unroll
        for (int n = 0; n < 8; n++) {
            float4 c = make_float4(0.f, 0.f, 0.f, 0.f);
            #pragma unroll
            for (int s = 0; s < 8; s++) {
                unsigned b0 = __float_as_uint(Ks[(8 * s + t) * KP + 8 * n + g]);
                unsigned b1 = __float_as_uint(Ks[(8 * s + t + 4) * KP + 8 * n + g]);
                mma8(c, aq[s][0], aq[s][1], aq[s][2], aq[s][3], b0, b1);
            }
            sacc[n] = c;
        }

        const bool wneed1 = (j0 <= i0 + rbase + 15);
        const bool wneed2 = (j0 + 63 >= i0 + rbase + 2);

        // ---- case-1 relative term ----
        if (wneed1) {
            #pragma unroll
            for (int n = 0; n < 10; n++) {
                float4 c = make_float4(0.f, 0.f, 0.f, 0.f);
                #pragma unroll
                for (int s = 0; s < 8; s++) {
                    unsigned b0 = __float_as_uint(W1[(8 * s + t) * WP + off1w + 8 * n + g]);
                    unsigned b1 = __float_as_uint(W1[(8 * s + t + 4) * WP + off1w + 8 * n + g]);
                    mma8(c, aq[s][0], aq[s][1], aq[s][2], aq[s][3], b0, b1);
                }
                wr0[8 * n] = c.x; wr0[8 * n + 1] = c.y;
                wr1[8 * n] = c.z; wr1[8 * n + 1] = c.w;
            }
            __syncwarp();
            #pragma unroll
            for (int n = 0; n < 8; n++) {
                int d00 = diffb + j0 + 8 * n;
                int tl = tlb + 8 * n;
                if (d00 <= 0)     sacc[n].x += rp0[tl];
                if (d00 + 1 <= 0) sacc[n].y += rp0[tl + 1];
                if (d00 - 8 <= 0) sacc[n].z += rp1[tl - 8];
                if (d00 - 7 <= 0) sacc[n].w += rp1[tl - 7];
            }
            __syncwarp();
        }
        // ---- case-2 relative term ----
        if (wneed2) {
            #pragma unroll
            for (int n = 0; n < 10; n++) {
                float4 c = make_float4(0.f, 0.f, 0.f, 0.f);
                #pragma unroll
                for (int s = 0; s < 8; s++) {
                    unsigned b0 = __float_as_uint(W2[(8 * s + t) * WP + off1w + 8 * n + g]);
                    unsigned b1 = __float_as_uint(W2[(8 * s + t + 4) * WP + off1w + 8 * n + g]);
                    mma8(c, aq2[s][0], aq2[s][1], aq2[s][2], aq2[s][3], b0, b1);
                }
                wr0[8 * n] = c.x; wr0[8 * n + 1] = c.y;
                wr1[8 * n] = c.z; wr1[8 * n + 1] = c.w;
            }
            __syncwarp();
            #pragma unroll
            for (int n = 0; n < 8; n++) {
                int d00 = diffb + j0 + 8 * n;
                int tl = tlb + 8 * n;
                if (d00 >= 2)     sacc[n].x += rp0[tl];
                if (d00 + 1 >= 2) sacc[n].y += rp0[tl + 1];
                if (d00 - 8 >= 2) sacc[n].z += rp1[tl - 8];
                if (d00 - 7 >= 2) sacc[n].w += rp1[tl - 7];
            }
            __syncwarp();
        }

        // ---- scale + online softmax ----
        float mx0 = -1e30f, mx1 = -1e30f;
        #pragma unroll
        for (int n = 0; n < 8; n++) {
            sacc[n].x *= SCALE; sacc[n].y *= SCALE;
            sacc[n].z *= SCALE; sacc[n].w *= SCALE;
            mx0 = fmaxf(mx0, fmaxf(sacc[n].x, sacc[n].y));
            mx1 = fmaxf(mx1, fmaxf(sacc[n].z, sacc[n].w));
        }
        #pragma unroll
        for (int off = 1; off <= 2; off <<= 1) {
            mx0 = fmaxf(mx0, __shfl_xor_sync(0xffffffffu, mx0, off));
            mx1 = fmaxf(mx1, __shfl_xor_sync(0xffffffffu, mx1, off));
        }
        float mn0 = fmaxf(m0r, mx0), mn1 = fmaxf(m1r, mx1);
        float c0 = __expf(m0r - mn0), c1 = __expf(m1r - mn1);
        float rs0 = 0.f, rs1 = 0.f;
        #pragma unroll
        for (int n = 0; n < 8; n++) {
            sacc[n].x = __expf(sacc[n].x - mn0);
            sacc[n].y = __expf(sacc[n].y - mn0);
            sacc[n].z = __expf(sacc[n].z - mn1);
            sacc[n].w = __expf(sacc[n].w - mn1);
            rs0 += sacc[n].x + sacc[n].y;
            rs1 += sacc[n].z + sacc[n].w;
        }
        #pragma unroll
        for (int off = 1; off <= 2; off <<= 1) {
            rs0 += __shfl_xor_sync(0xffffffffu, rs0, off);
            rs1 += __shfl_xor_sync(0xffffffffu, rs1, off);
        }
        l0r = l0r * c0 + rs0;  m0r = mn0;
        l1r = l1r * c1 + rs1;  m1r = mn1;
        #pragma unroll
        for (int n = 0; n < 8; n++) {
            Oacc[n].x *= c0; Oacc[n].y *= c0;
            Oacc[n].z *= c1; Oacc[n].w *= c1;
        }

        // ---- O += P V  (bf16 3-pass; A-frags straight from sacc) ----
        #pragma unroll
        for (int sp = 0; sp < 4; sp++) {
            float4 pa = sacc[2 * sp], pb = sacc[2 * sp + 1];
            unsigned ah0 = pk2(pa.y, pa.x), ah1 = pk2(pa.w, pa.z);
            unsigned ah2 = pk2(pb.y, pb.x), ah3 = pk2(pb.w, pb.z);
            unsigned al0 = pk2(pa.y - hi16f(ah0), pa.x - lo16f(ah0));
            unsigned al1 = pk2(pa.w - hi16f(ah1), pa.z - lo16f(ah1));
            unsigned al2 = pk2(pb.y - hi16f(ah2), pb.x - lo16f(ah2));
            unsigned al3 = pk2(pb.w - hi16f(ah3), pb.z - lo16f(ah3));
            #pragma unroll
            for (int np = 0; np < 8; np++) {
                unsigned bh0 = Vth[(8 * np + g) * 36 + 8 * sp + t];
                unsigned bh1 = Vth[(8 * np + g) * 36 + 8 * sp + t + 4];
                unsigned bl0 = Vtl[(8 * np + g) * 36 + 8 * sp + t];
                unsigned bl1 = Vtl[(8 * np + g) * 36 + 8 * sp + t + 4];
                mma16(Oacc[np], ah0, ah1, ah2, ah3, bh0, bh1);
                mma16(Oacc[np], ah0, ah1, ah2, ah3, bl0, bl1);
                mma16(Oacc[np], al0, al1, al2, al3, bh0, bh1);
            }
        }
    }

    // ---- normalize + write out [b][s][h*64+d] ----
    const int b_ = bh >> 3, h = bh & 7;
    const float inv0 = 1.0f / l0r, inv1 = 1.0f / l1r;
    float* op0 = out + ((size_t)b_ * SS + (i0 + rbase + g)) * EE + h * HD;
    float* op1 = out + ((size_t)b_ * SS + (i0 + rbase + g + 8)) * EE + h * HD;
    #pragma unroll
    for (int n = 0; n < 8; n++) {
        *(float2*)&op0[8 * n + 2 * t] = make_float2(Oacc[n].x * inv0, Oacc[n].y * inv0);
        *(float2*)&op1[8 * n + 2 * t] = make_float2(Oacc[n].z * inv1, Oacc[n].w * inv1);
    }
}

// ---------------------------------------------------------------------------
// Kernel 3: in-place LayerNorm over E=512 per (b,s) row.
// ---------------------------------------------------------------------------
__global__ void __launch_bounds__(256) ln_kernel(
    float* __restrict__ out,
    const float* __restrict__ gamma,
    const float* __restrict__ beta)
{
    __shared__ float red[16];
    const int row = blockIdx.x;
    float* p = out + (size_t)row * EE;
    const int tid = threadIdx.x;

    float v0 = p[tid], v1 = p[tid + 256];
    float s = v0 + v1;
    float q = v0 * v0 + v1 * v1;
    #pragma unroll
    for (int off = 16; off > 0; off >>= 1) {
        s += __shfl_xor_sync(0xffffffffu, s, off);
        q += __shfl_xor_sync(0xffffffffu, q, off);
    }
    const int wid = tid >> 5, lid = tid & 31;
    if (lid == 0) { red[wid] = s; red[8 + wid] = q; }
    __syncthreads();
    s = 0.0f; q = 0.0f;
    #pragma unroll
    for (int w = 0; w < 8; w++) { s += red[w]; q += red[8 + w]; }

    float mu = s * (1.0f / EE);
    float var = q * (1.0f / EE) - mu * mu;
    float inv = rsqrtf(var + 1e-5f);
    p[tid]       = (v0 - mu) * inv * gamma[tid]       + beta[tid];
    p[tid + 256] = (v1 - mu) * inv * gamma[tid + 256] + beta[tid + 256];
}

// ---------------------------------------------------------------------------
extern "C" void kernel_launch(void* const* d_in, const int* in_sizes, int n_in,
                              void* d_out, int out_size)
{
    const float* x     = (const float*)d_in[0];
    const float* Wq    = (const float*)d_in[1];
    const float* Wk    = (const float*)d_in[2];
    const float* Wv    = (const float*)d_in[3];
    const float* Er    = (const float*)d_in[4];
    const float* gamma = (const float*)d_in[5];
    const float* beta  = (const float*)d_in[6];
    float* out = (float*)d_out;

    cudaFuncSetAttribute(qkv_mma_kernel,
                         cudaFuncAttributeMaxDynamicSharedMemorySize, QKV_SMEM_BYTES);
    cudaFuncSetAttribute(attn_kernel,
                         cudaFuncAttributeMaxDynamicSharedMemorySize, SMEM_BYTES);

    qkv_mma_kernel<<<dim3(EE / 128, (BB * SS) / 128, 3), 256, QKV_SMEM_BYTES>>>(x, Wq, Wk, Wv);
    attn_kernel<<<dim3(SS / 128, BB * HH), 256, SMEM_BYTES>>>(Er, out);
    ln_kernel<<<BB * SS, 256>>>(out, gamma, beta);
}